// round 17
// baseline (speedup 1.0000x reference)
#include <cuda_runtime.h>
#include <cstdint>

// input : 2 tensors float32 [2048, 8, 8, 64]  (re, im)   8,388,608 elems each
// output: float32 [2, 2048, 8, 16, 64]                  33,554,432 elems
//
// Per block b (qubit q = 0 if b even else 5; mask m = 32 or 1):
//   top (d 0..7):  out[i] = S * in[i ^ m],              S = 2^-0.25
//   bot (d 8..15): out_re[i] = sgn * A * (re[i]-im[i])
//                  out_im[i] = sgn * A * (re[i]+im[i]), A = 2^-0.75,
//                  sgn = (i & m) ? -1 : +1
//
// Each thread owns the float4 pair {f, f^8} (single load per input float4).
// Stores use st.global.wt (write-through): output lines never sit dirty in
// L2, removing victim-eviction pacing from the DRAM write drain.

#define S_CONST 0.8408964152537145f   // 2^-0.25
#define A_CONST 0.5946035575013605f   // 2^-0.75

__device__ __forceinline__ float4 scale4(float4 v, float s) {
    return make_float4(s * v.x, s * v.y, s * v.z, s * v.w);
}
__device__ __forceinline__ float4 swap_scale4(float4 v, float s) {
    return make_float4(s * v.y, s * v.x, s * v.w, s * v.z);
}
__device__ __forceinline__ void stg_wt(float4* p, float4 v) {
    asm volatile("st.global.wt.v4.f32 [%0], {%1,%2,%3,%4};"
                 :: "l"(p), "f"(v.x), "f"(v.y), "f"(v.z), "f"(v.w)
                 : "memory");
}

__global__ void __launch_bounds__(256)
entangle_wt_kernel(const float4* __restrict__ re4,
                   const float4* __restrict__ im4,
                   float4* __restrict__ out4,
                   int n_pairs)   // 1,048,576
{
    int t = blockIdx.x * blockDim.x + threadIdx.x;
    if (t >= n_pairs) return;

    // decode: t = ((bblk*8 + d)*8 + i8)
    int i8   = t & 7;           // low float4 index (0..7); partner at i8+8
    int rest = t >> 3;
    int d    = rest & 7;
    int bblk = rest >> 3;       // b*8 + blk
    int blk  = bblk & 7;
    const bool even_blk = (blk & 1) == 0;   // qubit 0 (m=32) vs qubit 5 (m=1)

    int f_lo = (bblk << 7) + (d << 4) + i8;
    int f_hi = f_lo + 8;

    float4 r_lo = re4[f_lo];
    float4 r_hi = re4[f_hi];
    float4 m_lo = im4[f_lo];
    float4 m_hi = im4[f_hi];

    float4 tr_lo, tr_hi, ti_lo, ti_hi;   // top (X gate)
    float4 br_lo, br_hi, bi_lo, bi_hi;   // bot (Z gate)

    if (even_blk) {
        tr_lo = scale4(r_hi, S_CONST);  ti_lo = scale4(m_hi, S_CONST);
        tr_hi = scale4(r_lo, S_CONST);  ti_hi = scale4(m_lo, S_CONST);
        br_lo = make_float4( A_CONST * (r_lo.x - m_lo.x),  A_CONST * (r_lo.y - m_lo.y),
                             A_CONST * (r_lo.z - m_lo.z),  A_CONST * (r_lo.w - m_lo.w));
        bi_lo = make_float4( A_CONST * (r_lo.x + m_lo.x),  A_CONST * (r_lo.y + m_lo.y),
                             A_CONST * (r_lo.z + m_lo.z),  A_CONST * (r_lo.w + m_lo.w));
        br_hi = make_float4(-A_CONST * (r_hi.x - m_hi.x), -A_CONST * (r_hi.y - m_hi.y),
                            -A_CONST * (r_hi.z - m_hi.z), -A_CONST * (r_hi.w - m_hi.w));
        bi_hi = make_float4(-A_CONST * (r_hi.x + m_hi.x), -A_CONST * (r_hi.y + m_hi.y),
                            -A_CONST * (r_hi.z + m_hi.z), -A_CONST * (r_hi.w + m_hi.w));
    } else {
        tr_lo = swap_scale4(r_lo, S_CONST);  ti_lo = swap_scale4(m_lo, S_CONST);
        tr_hi = swap_scale4(r_hi, S_CONST);  ti_hi = swap_scale4(m_hi, S_CONST);
        br_lo = make_float4( A_CONST * (r_lo.x - m_lo.x), -A_CONST * (r_lo.y - m_lo.y),
                             A_CONST * (r_lo.z - m_lo.z), -A_CONST * (r_lo.w - m_lo.w));
        bi_lo = make_float4( A_CONST * (r_lo.x + m_lo.x), -A_CONST * (r_lo.y + m_lo.y),
                             A_CONST * (r_lo.z + m_lo.z), -A_CONST * (r_lo.w + m_lo.w));
        br_hi = make_float4( A_CONST * (r_hi.x - m_hi.x), -A_CONST * (r_hi.y - m_hi.y),
                             A_CONST * (r_hi.z - m_hi.z), -A_CONST * (r_hi.w - m_hi.w));
        bi_hi = make_float4( A_CONST * (r_hi.x + m_hi.x), -A_CONST * (r_hi.y + m_hi.y),
                             A_CONST * (r_hi.z + m_hi.z), -A_CONST * (r_hi.w + m_hi.w));
    }

    // output float4 layout: [2][2048][8][16][16f4]; part stride (imag) = PS4
    const int PS4 = 2048 * 8 * 16 * 16;             // 4,194,304
    int ot_lo = (bblk * 16 + d) * 16 + i8;          // top, lo float4
    int ot_hi = ot_lo + 8;
    int ob_lo = ot_lo + 8 * 16;                     // bot: row d+8
    int ob_hi = ob_lo + 8;

    stg_wt(&out4[ot_lo],       tr_lo);
    stg_wt(&out4[ot_hi],       tr_hi);
    stg_wt(&out4[ob_lo],       br_lo);
    stg_wt(&out4[ob_hi],       br_hi);
    stg_wt(&out4[ot_lo + PS4], ti_lo);
    stg_wt(&out4[ot_hi + PS4], ti_hi);
    stg_wt(&out4[ob_lo + PS4], bi_lo);
    stg_wt(&out4[ob_hi + PS4], bi_hi);
}

extern "C" void kernel_launch(void* const* d_in, const int* in_sizes, int n_in,
                              void* d_out, int out_size)
{
    const float4* re4 = (const float4*)d_in[0];
    const float4* im4 = (const float4*)d_in[1];
    float4* out4      = (float4*)d_out;

    int n_pairs = in_sizes[0] / 8;   // 1,048,576
    int threads = 256;
    int blocks  = (n_pairs + threads - 1) / threads;   // 4096

    entangle_wt_kernel<<<blocks, threads>>>(re4, im4, out4, n_pairs);
}